// round 16
// baseline (speedup 1.0000x reference)
#include <cuda_runtime.h>
#include <cuda_bf16.h>
#include <cstddef>

namespace {
constexpr int Bn = 4, Tn = 2048, Cn = 1024, Hn = 16, Dn = 64, Pn = 64;
constexpr int Mn = Bn * Tn;  // 8192
}

// Scratch (static device globals -- no runtime allocation)
__device__ float g_q[(size_t)Bn * Hn * Tn * Dn];    // [B,H,T,D]
__device__ float g_k[(size_t)Bn * Hn * Tn * Dn];
__device__ float g_v[(size_t)Bn * Hn * Tn * Dn];
__device__ float g_att[(size_t)Mn * Cn];            // [B*T, C]

// ---------------------------------------------------------------------------
// GEMM: Y[m,n] = sum_k X[m,k] * W[n,k] + bias[n]
// which: 0->g_q, 1->g_k, 2->g_v (head layout [B,H,T,D]); 3-> dout row-major,
//        and A input is g_att.
// 128x128 block, BK=8, 256 threads, 8x8 micro-tile.
// ---------------------------------------------------------------------------
__global__ void __launch_bounds__(256, 2)
gemm_nt(const float* __restrict__ X, const float* __restrict__ W,
        const float* __restrict__ bias, float* __restrict__ dout, int which)
{
    constexpr int K = Cn;
    const float* A = (which == 3) ? (const float*)g_att : X;
    float* out;
    if (which == 0)      out = g_q;
    else if (which == 1) out = g_k;
    else if (which == 2) out = g_v;
    else                 out = dout;
    const bool head_layout = (which < 3);

    __shared__ float As[8][132];
    __shared__ float Bs[8][132];

    const int tid  = threadIdx.x;
    const int bm   = blockIdx.y * 128;
    const int bn   = blockIdx.x * 128;
    const int lrow = tid >> 1;            // 0..127
    const int lcol = (tid & 1) << 2;      // 0 or 4
    const int tx   = tid & 15;
    const int ty   = tid >> 4;

    const float* Ap = A + (size_t)(bm + lrow) * K + lcol;
    const float* Wp = W + (size_t)(bn + lrow) * K + lcol;

    float4 af = *(const float4*)Ap;
    float4 wf = *(const float4*)Wp;

    float acc[8][8];
#pragma unroll
    for (int i = 0; i < 8; i++)
#pragma unroll
        for (int j = 0; j < 8; j++) acc[i][j] = 0.f;

    for (int k0 = 0; k0 < K; k0 += 8) {
        As[lcol + 0][lrow] = af.x;
        As[lcol + 1][lrow] = af.y;
        As[lcol + 2][lrow] = af.z;
        As[lcol + 3][lrow] = af.w;
        Bs[lcol + 0][lrow] = wf.x;
        Bs[lcol + 1][lrow] = wf.y;
        Bs[lcol + 2][lrow] = wf.z;
        Bs[lcol + 3][lrow] = wf.w;
        __syncthreads();
        if (k0 + 8 < K) {
            af = *(const float4*)(Ap + k0 + 8);
            wf = *(const float4*)(Wp + k0 + 8);
        }
#pragma unroll
        for (int kk = 0; kk < 8; kk++) {
            float a[8], bb[8];
            *(float4*)&a[0]  = *(const float4*)&As[kk][ty * 8];
            *(float4*)&a[4]  = *(const float4*)&As[kk][ty * 8 + 4];
            *(float4*)&bb[0] = *(const float4*)&Bs[kk][tx * 8];
            *(float4*)&bb[4] = *(const float4*)&Bs[kk][tx * 8 + 4];
#pragma unroll
            for (int i = 0; i < 8; i++)
#pragma unroll
                for (int j = 0; j < 8; j++)
                    acc[i][j] = fmaf(a[i], bb[j], acc[i][j]);
        }
        __syncthreads();
    }

#pragma unroll
    for (int i = 0; i < 8; i++) {
        const int m = bm + ty * 8 + i;
        const int b = m >> 11;            // / Tn
        const int t = m & (Tn - 1);
#pragma unroll
        for (int j = 0; j < 8; j += 4) {
            const int n = bn + tx * 8 + j;
            float4 r;
            r.x = acc[i][j + 0] + bias[n + 0];
            r.y = acc[i][j + 1] + bias[n + 1];
            r.z = acc[i][j + 2] + bias[n + 2];
            r.w = acc[i][j + 3] + bias[n + 3];
            if (head_layout) {
                const int h = n >> 6, d = n & 63;
                *(float4*)&out[((size_t)(b * Hn + h) * Tn + t) * Dn + d] = r;
            } else {
                *(float4*)&out[(size_t)m * Cn + n] = r;
            }
        }
    }
}

// ---------------------------------------------------------------------------
// Flash attention over S = P + T keys. One block per (b, h, 64-query tile).
// Tile 0 = prefix (always visible); tiles 1..32 = projected K/V with per-key
// mask. 256 threads, 4x4 register tiles. Smem = exactly 48KB (static).
// ---------------------------------------------------------------------------
__global__ void __launch_bounds__(256)
attn64(const int* __restrict__ mask, const float* __restrict__ pk,
       const float* __restrict__ pv)
{
    __shared__ float Qs[64 * 64];   // transposed: Qs[d*64 + q], pre-scaled
    __shared__ float KPs[64 * 64];  // phase 1: K transposed [d*64 + kk];
                                    // phase 2: P row-major   [q*64 + kk]
    __shared__ float Vs[64 * 64];   // Vs[kk*64 + d]

    const int tid = threadIdx.x;
    const int t0  = blockIdx.x * 64;
    const int h   = blockIdx.y;
    const int b   = blockIdx.z;
    const int tx  = tid & 15;       // k / d column group
    const int ty  = tid >> 4;       // q row group

    const float* qb  = g_q + ((size_t)(b * Hn + h) * Tn + t0) * Dn;
    const float* kb  = g_k + (size_t)(b * Hn + h) * Tn * Dn;
    const float* vb  = g_v + (size_t)(b * Hn + h) * Tn * Dn;
    const float* pkb = pk + (size_t)(b * Hn + h) * Pn * Dn;
    const float* pvb = pv + (size_t)(b * Hn + h) * Pn * Dn;
    const int*   mb  = mask + b * Tn;

    const int lr = tid >> 2;          // 0..63 : row
    const int lc = (tid & 3) << 4;    // 0,16,32,48 : col base

    // Load Q tile transposed, pre-scaled by 1/sqrt(D)
#pragma unroll
    for (int u = 0; u < 4; u++) {
        float4 f = *(const float4*)(qb + lr * Dn + lc + u * 4);
        Qs[(lc + u * 4 + 0) * 64 + lr] = f.x * 0.125f;
        Qs[(lc + u * 4 + 1) * 64 + lr] = f.y * 0.125f;
        Qs[(lc + u * 4 + 2) * 64 + lr] = f.z * 0.125f;
        Qs[(lc + u * 4 + 3) * 64 + lr] = f.w * 0.125f;
    }

    float mI[4], lI[4], oA[4][4];
#pragma unroll
    for (int i = 0; i < 4; i++) {
        mI[i] = -1e30f;
        lI[i] = 0.f;
#pragma unroll
        for (int j = 0; j < 4; j++) oA[i][j] = 0.f;
    }

    constexpr int NT = 1 + Tn / 64;   // 33 key tiles

    for (int ti = 0; ti < NT; ti++) {
        __syncthreads();  // previous PV done reading KPs/Vs (also covers Qs on ti=0)

        const float* ks = (ti == 0) ? pkb : (kb + (size_t)(ti - 1) * 64 * Dn);
        const float* vs = (ti == 0) ? pvb : (vb + (size_t)(ti - 1) * 64 * Dn);
#pragma unroll
        for (int u = 0; u < 4; u++) {
            float4 f = *(const float4*)(ks + lr * Dn + lc + u * 4);
            KPs[(lc + u * 4 + 0) * 64 + lr] = f.x;
            KPs[(lc + u * 4 + 1) * 64 + lr] = f.y;
            KPs[(lc + u * 4 + 2) * 64 + lr] = f.z;
            KPs[(lc + u * 4 + 3) * 64 + lr] = f.w;
            float4 g = *(const float4*)(vs + lr * Dn + lc + u * 4);
            *(float4*)&Vs[lr * 64 + lc + u * 4] = g;
        }

        // Per-key additive mask for this thread's 4 key columns
        float mj[4];
        if (ti == 0) {
            mj[0] = mj[1] = mj[2] = mj[3] = 0.f;
        } else {
            int4 mi = *(const int4*)(mb + (ti - 1) * 64 + tx * 4);
            mj[0] = mi.x ? 0.f : -1e30f;
            mj[1] = mi.y ? 0.f : -1e30f;
            mj[2] = mi.z ? 0.f : -1e30f;
            mj[3] = mi.w ? 0.f : -1e30f;
        }
        __syncthreads();  // K/V tiles ready

        // S = Q*K^T (4x4 per thread), seeded with mask
        float sv[4][4];
#pragma unroll
        for (int i = 0; i < 4; i++)
#pragma unroll
            for (int j = 0; j < 4; j++) sv[i][j] = mj[j];

#pragma unroll 16
        for (int kk = 0; kk < 64; kk++) {
            float4 qa = *(const float4*)&Qs[kk * 64 + ty * 4];
            float4 ka = *(const float4*)&KPs[kk * 64 + tx * 4];
            const float aa[4] = {qa.x, qa.y, qa.z, qa.w};
            const float bbv[4] = {ka.x, ka.y, ka.z, ka.w};
#pragma unroll
            for (int i = 0; i < 4; i++)
#pragma unroll
                for (int j = 0; j < 4; j++)
                    sv[i][j] = fmaf(aa[i], bbv[j], sv[i][j]);
        }
        __syncthreads();  // everyone done reading K before P overwrites KPs

        // Online softmax update (row stats shared across the 16-lane group
        // with equal ty: lanes (ty&1)*16 + tx, so xor offsets <= 8 stay inside)
#pragma unroll
        for (int i = 0; i < 4; i++) {
            float tm = fmaxf(fmaxf(sv[i][0], sv[i][1]), fmaxf(sv[i][2], sv[i][3]));
#pragma unroll
            for (int off = 8; off >= 1; off >>= 1)
                tm = fmaxf(tm, __shfl_xor_sync(0xffffffffu, tm, off));
            const float mn = fmaxf(mI[i], tm);
            const float alpha = __expf(mI[i] - mn);
            mI[i] = mn;
            float ls = 0.f;
#pragma unroll
            for (int j = 0; j < 4; j++) {
                const float p = __expf(sv[i][j] - mn);
                sv[i][j] = p;
                ls += p;
            }
#pragma unroll
            for (int off = 8; off >= 1; off >>= 1)
                ls += __shfl_xor_sync(0xffffffffu, ls, off);
            lI[i] = lI[i] * alpha + ls;
#pragma unroll
            for (int j = 0; j < 4; j++) oA[i][j] *= alpha;
            *(float4*)&KPs[(ty * 4 + i) * 64 + tx * 4] =
                make_float4(sv[i][0], sv[i][1], sv[i][2], sv[i][3]);
        }
        __syncthreads();  // P visible

        // O += P * V
#pragma unroll 16
        for (int kk = 0; kk < 64; kk++) {
            float4 vv = *(const float4*)&Vs[kk * 64 + tx * 4];
            const float p0 = KPs[(ty * 4 + 0) * 64 + kk];
            const float p1 = KPs[(ty * 4 + 1) * 64 + kk];
            const float p2 = KPs[(ty * 4 + 2) * 64 + kk];
            const float p3 = KPs[(ty * 4 + 3) * 64 + kk];
            oA[0][0] = fmaf(p0, vv.x, oA[0][0]);
            oA[0][1] = fmaf(p0, vv.y, oA[0][1]);
            oA[0][2] = fmaf(p0, vv.z, oA[0][2]);
            oA[0][3] = fmaf(p0, vv.w, oA[0][3]);
            oA[1][0] = fmaf(p1, vv.x, oA[1][0]);
            oA[1][1] = fmaf(p1, vv.y, oA[1][1]);
            oA[1][2] = fmaf(p1, vv.z, oA[1][2]);
            oA[1][3] = fmaf(p1, vv.w, oA[1][3]);
            oA[2][0] = fmaf(p2, vv.x, oA[2][0]);
            oA[2][1] = fmaf(p2, vv.y, oA[2][1]);
            oA[2][2] = fmaf(p2, vv.z, oA[2][2]);
            oA[2][3] = fmaf(p2, vv.w, oA[2][3]);
            oA[3][0] = fmaf(p3, vv.x, oA[3][0]);
            oA[3][1] = fmaf(p3, vv.y, oA[3][1]);
            oA[3][2] = fmaf(p3, vv.z, oA[3][2]);
            oA[3][3] = fmaf(p3, vv.w, oA[3][3]);
        }
    }

    // Normalize and write to g_att in [B,T,C] layout (C index = h*64 + d)
#pragma unroll
    for (int i = 0; i < 4; i++) {
        const float inv = 1.f / lI[i];
        const int t = t0 + ty * 4 + i;
        float4 r = make_float4(oA[i][0] * inv, oA[i][1] * inv,
                               oA[i][2] * inv, oA[i][3] * inv);
        *(float4*)&g_att[((size_t)b * Tn + t) * Cn + h * Dn + tx * 4] = r;
    }
}

// ---------------------------------------------------------------------------
extern "C" void kernel_launch(void* const* d_in, const int* in_sizes, int n_in,
                              void* d_out, int out_size)
{
    const float* x         = (const float*)d_in[0];
    const int*   attn_mask = (const int*)  d_in[1];
    const float* prefix_k  = (const float*)d_in[2];
    const float* prefix_v  = (const float*)d_in[3];
    const float* Wq        = (const float*)d_in[4];
    const float* bq        = (const float*)d_in[5];
    const float* Wk        = (const float*)d_in[6];
    const float* bk        = (const float*)d_in[7];
    const float* Wv        = (const float*)d_in[8];
    const float* bv        = (const float*)d_in[9];
    const float* Wo        = (const float*)d_in[10];
    const float* bo        = (const float*)d_in[11];
    float* out = (float*)d_out;

    const dim3 ggrid(Cn / 128, Mn / 128);   // (8, 64)
    gemm_nt<<<ggrid, 256>>>(x, Wq, bq, nullptr, 0);
    gemm_nt<<<ggrid, 256>>>(x, Wk, bk, nullptr, 1);
    gemm_nt<<<ggrid, 256>>>(x, Wv, bv, nullptr, 2);

    attn64<<<dim3(Tn / 64, Hn, Bn), 256>>>(attn_mask, prefix_k, prefix_v);

    gemm_nt<<<ggrid, 256>>>(nullptr, Wo, bo, out, 3);
}